// round 13
// baseline (speedup 1.0000x reference)
#include <cuda_runtime.h>
#include <cuda_fp16.h>
#include <mma.h>
#include <cstdint>

using namespace nvcuda;

#define N_NODES_MAX 100000
#define NFEAT 128

// Scratch (allocation-free rule: __device__ globals, referenced only in kernels)
__device__ __half g_XFh[(size_t)N_NODES_MAX * NFEAT];   // XF in fp16
__device__ __half g_Fh[NFEAT * NFEAT];                  // filters in fp16
__device__ int    g_rowptr[N_NODES_MAX + 1];            // CSR row pointer

// ---------------------------------------------------------------------------
// Kernel A: rowptr from sorted edge_dst — 4 edges/thread, one int4 load.
// ---------------------------------------------------------------------------
__global__ void rowptr_kernel(const int* __restrict__ edst, int E, int N) {
    const int t  = blockIdx.x * blockDim.x + threadIdx.x;
    const int e0 = t * 4;
    if (e0 >= E) return;

    int d[4];
    int nvalid;
    if (e0 + 4 <= E) {
        const int4 d4 = __ldg((const int4*)(edst + e0));
        d[0] = d4.x; d[1] = d4.y; d[2] = d4.z; d[3] = d4.w;
        nvalid = 4;
    } else {
        nvalid = E - e0;
        for (int i = 0; i < nvalid; i++) d[i] = __ldg(edst + e0 + i);
    }

    int prev = (e0 == 0) ? -1 : __ldg(edst + e0 - 1);
#pragma unroll
    for (int i = 0; i < 4; i++) {
        if (i < nvalid) {
            for (int dd = prev + 1; dd <= d[i]; dd++) g_rowptr[dd] = e0 + i;
            prev = d[i];
        }
    }
    if (e0 + 4 >= E) {
        for (int dd = prev + 1; dd <= N; dd++) g_rowptr[dd] = E;
    }
}

// ---------------------------------------------------------------------------
// Kernel B0: filters fp32 -> fp16 (one-time tiny convert)
// ---------------------------------------------------------------------------
__global__ void fconv_kernel(const float* __restrict__ F) {
    int i = blockIdx.x * blockDim.x + threadIdx.x;
    if (i < NFEAT * NFEAT) g_Fh[i] = __float2half_rn(F[i]);
}

// ---------------------------------------------------------------------------
// Kernel B: tensor-core GEMM  XF[M,128] = x[M,128] @ filters[128,128]
// fp16 HMMA, fp32 accumulate, fp16 output. BM=64, 3 blocks/SM.
// ---------------------------------------------------------------------------
#define GB_BM 64
#define LDM 136   // 128 + 8 halves pad

__global__ __launch_bounds__(256)
void gemm_wmma_kernel(const float* __restrict__ A, int M) {
    __shared__ __half Bs[NFEAT][LDM];
    __shared__ __half As[GB_BM][LDM];
    __shared__ float  stage[8][16 * 16];

    const int tid  = threadIdx.x;
    const int warp = tid >> 5;
    const int lane = tid & 31;
    const int block_row = blockIdx.x * GB_BM;

#pragma unroll
    for (int i = 0; i < 8; i++) {
        const int g   = tid + i * 256;
        const int row = g >> 4;
        const int col = (g & 15) << 3;
        const uint4 v = *(const uint4*)(g_Fh + (size_t)row * NFEAT + col);
        *(uint4*)&Bs[row][col] = v;
    }

#pragma unroll
    for (int i = 0; i < 8; i++) {
        const int idx = tid + i * 256;
        const int row = idx >> 5;
        const int col = (idx & 31) << 2;
        const int gr  = block_row + row;
        float4 v;
        if (gr < M)
            v = *(const float4*)(A + (size_t)gr * NFEAT + col);
        else
            v = make_float4(0.f, 0.f, 0.f, 0.f);
        *(__half2*)&As[row][col + 0] = __floats2half2_rn(v.x, v.y);
        *(__half2*)&As[row][col + 2] = __floats2half2_rn(v.z, v.w);
    }
    __syncthreads();

    const int srow = (warp >> 1) * 16;
    const int scol = (warp & 1) * 64;

    wmma::fragment<wmma::accumulator, 16, 16, 16, float> acc[4];
#pragma unroll
    for (int ct = 0; ct < 4; ct++) wmma::fill_fragment(acc[ct], 0.0f);

#pragma unroll
    for (int kt = 0; kt < 8; kt++) {
        wmma::fragment<wmma::matrix_a, 16, 16, 16, __half, wmma::row_major> a_frag;
        wmma::load_matrix_sync(a_frag, &As[srow][kt * 16], LDM);
#pragma unroll
        for (int ct = 0; ct < 4; ct++) {
            wmma::fragment<wmma::matrix_b, 16, 16, 16, __half, wmma::row_major> b_frag;
            wmma::load_matrix_sync(b_frag, &Bs[kt * 16][scol + ct * 16], LDM);
            wmma::mma_sync(acc[ct], a_frag, b_frag, acc[ct]);
        }
    }

    const int r  = lane >> 1;
    const int c0 = (lane & 1) * 8;
#pragma unroll
    for (int ct = 0; ct < 4; ct++) {
        wmma::store_matrix_sync(&stage[warp][0], acc[ct], 16, wmma::mem_row_major);
        __syncwarp();
        const float* sp = &stage[warp][r * 16 + c0];
        __half2 h[4];
#pragma unroll
        for (int j = 0; j < 4; j++)
            h[j] = __floats2half2_rn(sp[2 * j], sp[2 * j + 1]);
        const int gr = block_row + srow + r;
        if (gr < M)
            *(uint4*)(g_XFh + (size_t)gr * NFEAT + scol + ct * 16 + c0) = *(const uint4*)h;
        __syncwarp();
    }
}

// ---------------------------------------------------------------------------
// Kernel C: SpMM — warp per dst node.
// Hot loop: fp16 HFMA2 math on DUAL chain-pairs (edges alternate chains),
// fp32 flush every 8 edges. Per-edge: 1 gather + 1 F2FP + 2 HFMA2 (+2.5
// flush-amortized) vs fp32 path's 4 F2F + 4 FFMA.
// ---------------------------------------------------------------------------
__device__ __forceinline__ void cvt_fma(float4& acc, uint2 hv, float w) {
    const float2 f0 = __half22float2(*reinterpret_cast<const __half2*>(&hv.x));
    const float2 f1 = __half22float2(*reinterpret_cast<const __half2*>(&hv.y));
    acc.x += w * f0.x;
    acc.y += w * f0.y;
    acc.z += w * f1.x;
    acc.w += w * f1.y;
}

__device__ __forceinline__ __half2 lo_h2(uint2 v) {
    return *reinterpret_cast<const __half2*>(&v.x);
}
__device__ __forceinline__ __half2 hi_h2(uint2 v) {
    return *reinterpret_cast<const __half2*>(&v.y);
}

__global__ __launch_bounds__(256)
void spmm_kernel(const int* __restrict__ esrc,
                 const float* __restrict__ ew,
                 float* __restrict__ out,
                 int N) {
    const int warp = (blockIdx.x * blockDim.x + threadIdx.x) >> 5;
    const int lane = threadIdx.x & 31;
    if (warp >= N) return;

    const int start = g_rowptr[warp];
    const int end   = g_rowptr[warp + 1];

    const __half* __restrict__ base = g_XFh + lane * 4;

    float4 acc = make_float4(0.f, 0.f, 0.f, 0.f);

    int e = start;
    // Head: reach 16B alignment (fp32 path, few edges)
    while (e < end && (e & 3)) {
        const uint2 hv = *(const uint2*)(base + (size_t)__ldg(esrc + e) * NFEAT);
        cvt_fma(acc, hv, __ldg(ew + e));
        e++;
    }

    const __half2 hz = __float2half2_rn(0.f);

    // Main: 8 edges — dual fp16 chain-pairs (A: a0/a1, B: b0/b1), flush to fp32
    for (; e + 8 <= end; e += 8) {
        const int4   sa = __ldg((const int4*)(esrc + e));
        const int4   sb = __ldg((const int4*)(esrc + e + 4));
        const float4 wa = __ldg((const float4*)(ew + e));
        const float4 wb = __ldg((const float4*)(ew + e + 4));

        const uint2 h0 = *(const uint2*)(base + (size_t)sa.x * NFEAT);
        const uint2 h1 = *(const uint2*)(base + (size_t)sa.y * NFEAT);
        const uint2 h2 = *(const uint2*)(base + (size_t)sa.z * NFEAT);
        const uint2 h3 = *(const uint2*)(base + (size_t)sa.w * NFEAT);
        const uint2 h4 = *(const uint2*)(base + (size_t)sb.x * NFEAT);
        const uint2 h5 = *(const uint2*)(base + (size_t)sb.y * NFEAT);
        const uint2 h6 = *(const uint2*)(base + (size_t)sb.z * NFEAT);
        const uint2 h7 = *(const uint2*)(base + (size_t)sb.w * NFEAT);

        const __half2 w0 = __float2half2_rn(wa.x);
        const __half2 w1 = __float2half2_rn(wa.y);
        const __half2 w2 = __float2half2_rn(wa.z);
        const __half2 w3 = __float2half2_rn(wa.w);
        const __half2 w4 = __float2half2_rn(wb.x);
        const __half2 w5 = __float2half2_rn(wb.y);
        const __half2 w6 = __float2half2_rn(wb.z);
        const __half2 w7 = __float2half2_rn(wb.w);

        __half2 a0 = hz, a1 = hz, b0 = hz, b1 = hz;
        // Even edges -> chain A, odd -> chain B (dep spacing = 4 instrs)
        a0 = __hfma2(w0, lo_h2(h0), a0);  a1 = __hfma2(w0, hi_h2(h0), a1);
        b0 = __hfma2(w1, lo_h2(h1), b0);  b1 = __hfma2(w1, hi_h2(h1), b1);
        a0 = __hfma2(w2, lo_h2(h2), a0);  a1 = __hfma2(w2, hi_h2(h2), a1);
        b0 = __hfma2(w3, lo_h2(h3), b0);  b1 = __hfma2(w3, hi_h2(h3), b1);
        a0 = __hfma2(w4, lo_h2(h4), a0);  a1 = __hfma2(w4, hi_h2(h4), a1);
        b0 = __hfma2(w5, lo_h2(h5), b0);  b1 = __hfma2(w5, hi_h2(h5), b1);
        a0 = __hfma2(w6, lo_h2(h6), a0);  a1 = __hfma2(w6, hi_h2(h6), a1);
        b0 = __hfma2(w7, lo_h2(h7), b0);  b1 = __hfma2(w7, hi_h2(h7), b1);

        // Flush both chains to fp32
        const float2 pa0 = __half22float2(a0);
        const float2 pa1 = __half22float2(a1);
        const float2 pb0 = __half22float2(b0);
        const float2 pb1 = __half22float2(b1);
        acc.x += pa0.x + pb0.x;
        acc.y += pa0.y + pb0.y;
        acc.z += pa1.x + pb1.x;
        acc.w += pa1.y + pb1.y;
    }

    // Mid: one 4-edge block (fp16, chains depth 2)
    for (; e + 4 <= end; e += 4) {
        const int4   sa = __ldg((const int4*)(esrc + e));
        const float4 wa = __ldg((const float4*)(ew + e));
        const uint2 h0 = *(const uint2*)(base + (size_t)sa.x * NFEAT);
        const uint2 h1 = *(const uint2*)(base + (size_t)sa.y * NFEAT);
        const uint2 h2 = *(const uint2*)(base + (size_t)sa.z * NFEAT);
        const uint2 h3 = *(const uint2*)(base + (size_t)sa.w * NFEAT);
        const __half2 w0 = __float2half2_rn(wa.x);
        const __half2 w1 = __float2half2_rn(wa.y);
        const __half2 w2 = __float2half2_rn(wa.z);
        const __half2 w3 = __float2half2_rn(wa.w);
        __half2 a0 = hz, a1 = hz, b0 = hz, b1 = hz;
        a0 = __hfma2(w0, lo_h2(h0), a0);  a1 = __hfma2(w0, hi_h2(h0), a1);
        b0 = __hfma2(w1, lo_h2(h1), b0);  b1 = __hfma2(w1, hi_h2(h1), b1);
        a0 = __hfma2(w2, lo_h2(h2), a0);  a1 = __hfma2(w2, hi_h2(h2), a1);
        b0 = __hfma2(w3, lo_h2(h3), b0);  b1 = __hfma2(w3, hi_h2(h3), b1);
        const float2 pa0 = __half22float2(a0);
        const float2 pa1 = __half22float2(a1);
        const float2 pb0 = __half22float2(b0);
        const float2 pb1 = __half22float2(b1);
        acc.x += pa0.x + pb0.x;
        acc.y += pa0.y + pb0.y;
        acc.z += pa1.x + pb1.x;
        acc.w += pa1.y + pb1.y;
    }

    // Tail (fp32 path)
    for (; e < end; e++) {
        const uint2 hv = *(const uint2*)(base + (size_t)__ldg(esrc + e) * NFEAT);
        cvt_fma(acc, hv, __ldg(ew + e));
    }

    *(float4*)(out + (size_t)warp * NFEAT + (size_t)lane * 4) = acc;
}

// ---------------------------------------------------------------------------
// Launch: rowptr -> fconv -> gemm -> spmm (graph-capturable)
// ---------------------------------------------------------------------------
extern "C" void kernel_launch(void* const* d_in, const int* in_sizes, int n_in,
                              void* d_out, int out_size) {
    const float* x       = (const float*)d_in[0];
    const float* filters = (const float*)d_in[1];
    const int*   esrc    = (const int*)d_in[2];
    const int*   edst    = (const int*)d_in[3];
    const float* ew      = (const float*)d_in[4];
    float*       out     = (float*)d_out;

    const int M = in_sizes[0] / NFEAT;   // 100000 nodes
    const int E = in_sizes[4];           // 3200000 edges

    const int rthreads = (E + 3) / 4;
    rowptr_kernel<<<(rthreads + 255) / 256, 256>>>(edst, E, M);
    fconv_kernel<<<(NFEAT * NFEAT + 255) / 256, 256>>>(filters);
    gemm_wmma_kernel<<<(M + GB_BM - 1) / GB_BM, 256>>>(x, M);

    const long long nthreads = (long long)M * 32;
    spmm_kernel<<<(int)((nthreads + 255) / 256), 256>>>(esrc, ew, out, M);
}

// round 14
// speedup vs baseline: 1.1068x; 1.1068x over previous
#include <cuda_runtime.h>
#include <cuda_fp16.h>
#include <mma.h>
#include <cstdint>

using namespace nvcuda;

#define N_NODES_MAX 100000
#define NFEAT 128

// Scratch (allocation-free rule: __device__ globals, referenced only in kernels)
__device__ __half g_XFh[(size_t)N_NODES_MAX * NFEAT];   // XF in fp16
__device__ int    g_rowptr[N_NODES_MAX + 1];            // CSR row pointer

// ---------------------------------------------------------------------------
// Fused prep kernel: blocks [0, gblocks) = GEMM tiles (with inline filter
// fp32->fp16 conversion), blocks [gblocks, ...) = rowptr from sorted edge_dst.
// One launch, independent work overlapped across SMs.
// ---------------------------------------------------------------------------
#define GB_BM 64
#define LDM 136   // 128 + 8 halves pad

__global__ __launch_bounds__(256)
void prep_kernel(const float* __restrict__ A,        // x [M,128]
                 const float* __restrict__ F,        // filters [128,128] fp32
                 const int*   __restrict__ edst,     // sorted dst [E]
                 int M, int E, int gblocks) {
    __shared__ __half Bs[NFEAT][LDM];          // filters fp16, 34.8KB
    __shared__ __half As[GB_BM][LDM];          // x tile fp16, 17.4KB
    __shared__ float  stage[8][16 * 16];       // per-warp staging, 8KB

    const int tid = threadIdx.x;

    if (blockIdx.x >= gblocks) {
        // ---------------- rowptr part: 4 edges/thread, one int4 load --------
        const int t  = (blockIdx.x - gblocks) * 256 + tid;
        const int e0 = t * 4;
        if (e0 >= E) return;

        int d[4];
        int nvalid;
        if (e0 + 4 <= E) {
            const int4 d4 = __ldg((const int4*)(edst + e0));
            d[0] = d4.x; d[1] = d4.y; d[2] = d4.z; d[3] = d4.w;
            nvalid = 4;
        } else {
            nvalid = E - e0;
            for (int i = 0; i < nvalid; i++) d[i] = __ldg(edst + e0 + i);
        }

        int prev = (e0 == 0) ? -1 : __ldg(edst + e0 - 1);
#pragma unroll
        for (int i = 0; i < 4; i++) {
            if (i < nvalid) {
                for (int dd = prev + 1; dd <= d[i]; dd++) g_rowptr[dd] = e0 + i;
                prev = d[i];
            }
        }
        if (e0 + 4 >= E) {
            for (int dd = prev + 1; dd <= M; dd++) g_rowptr[dd] = E;
        }
        return;
    }

    // ---------------- GEMM part: XF[64,128] tile ---------------------------
    const int warp = tid >> 5;
    const int lane = tid & 31;
    const int block_row = blockIdx.x * GB_BM;

    // Inline filter convert: 4096 float4 groups, 16 per thread (coalesced)
#pragma unroll
    for (int i = 0; i < 16; i++) {
        const int g   = tid + i * 256;          // 0..4095
        const int row = g >> 5;                 // 32 float4 per 128-col row
        const int col = (g & 31) << 2;
        const float4 v = *(const float4*)(F + (size_t)row * NFEAT + col);
        *(__half2*)&Bs[row][col + 0] = __floats2half2_rn(v.x, v.y);
        *(__half2*)&Bs[row][col + 2] = __floats2half2_rn(v.z, v.w);
    }

    // Load + convert x tile: 64x128 fp32 -> fp16 SMEM (8 float4 per thread)
#pragma unroll
    for (int i = 0; i < 8; i++) {
        const int idx = tid + i * 256;          // 0..2047
        const int row = idx >> 5;
        const int col = (idx & 31) << 2;
        const int gr  = block_row + row;
        float4 v;
        if (gr < M)
            v = *(const float4*)(A + (size_t)gr * NFEAT + col);
        else
            v = make_float4(0.f, 0.f, 0.f, 0.f);
        *(__half2*)&As[row][col + 0] = __floats2half2_rn(v.x, v.y);
        *(__half2*)&As[row][col + 2] = __floats2half2_rn(v.z, v.w);
    }
    __syncthreads();

    // MMA: warp owns 16 rows x 64 cols
    const int srow = (warp >> 1) * 16;
    const int scol = (warp & 1) * 64;

    wmma::fragment<wmma::accumulator, 16, 16, 16, float> acc[4];
#pragma unroll
    for (int ct = 0; ct < 4; ct++) wmma::fill_fragment(acc[ct], 0.0f);

#pragma unroll
    for (int kt = 0; kt < 8; kt++) {
        wmma::fragment<wmma::matrix_a, 16, 16, 16, __half, wmma::row_major> a_frag;
        wmma::load_matrix_sync(a_frag, &As[srow][kt * 16], LDM);
#pragma unroll
        for (int ct = 0; ct < 4; ct++) {
            wmma::fragment<wmma::matrix_b, 16, 16, 16, __half, wmma::row_major> b_frag;
            wmma::load_matrix_sync(b_frag, &Bs[kt * 16][scol + ct * 16], LDM);
            wmma::mma_sync(acc[ct], a_frag, b_frag, acc[ct]);
        }
    }

    // Store: stage f32 per col-tile, convert to fp16, 16B/thread writes
    const int r  = lane >> 1;
    const int c0 = (lane & 1) * 8;
#pragma unroll
    for (int ct = 0; ct < 4; ct++) {
        wmma::store_matrix_sync(&stage[warp][0], acc[ct], 16, wmma::mem_row_major);
        __syncwarp();
        const float* sp = &stage[warp][r * 16 + c0];
        __half2 h[4];
#pragma unroll
        for (int j = 0; j < 4; j++)
            h[j] = __floats2half2_rn(sp[2 * j], sp[2 * j + 1]);
        const int gr = block_row + srow + r;
        if (gr < M)
            *(uint4*)(g_XFh + (size_t)gr * NFEAT + scol + ct * 16 + c0) = *(const uint4*)h;
        __syncwarp();
    }
}

// ---------------------------------------------------------------------------
// Kernel C: SpMM — warp per dst node (round-7 exact shape: regs 32, occ 82%).
// fp32 accumulation, vectorized idx/weight loads, unroll 8.
// ---------------------------------------------------------------------------
__device__ __forceinline__ void edge_acc(float4& acc, int s, float w, int lane) {
    const uint2 hv = *(const uint2*)(g_XFh + (size_t)s * NFEAT + lane * 4);
    const float2 f0 = __half22float2(*reinterpret_cast<const __half2*>(&hv.x));
    const float2 f1 = __half22float2(*reinterpret_cast<const __half2*>(&hv.y));
    acc.x += w * f0.x;
    acc.y += w * f0.y;
    acc.z += w * f1.x;
    acc.w += w * f1.y;
}

__global__ __launch_bounds__(256)
void spmm_kernel(const int* __restrict__ esrc,
                 const float* __restrict__ ew,
                 float* __restrict__ out,
                 int N) {
    const int warp = (blockIdx.x * blockDim.x + threadIdx.x) >> 5;
    const int lane = threadIdx.x & 31;
    if (warp >= N) return;

    const int start = g_rowptr[warp];
    const int end   = g_rowptr[warp + 1];

    float4 acc = make_float4(0.f, 0.f, 0.f, 0.f);

    int e = start;
    // Head: reach 16B alignment for int4/float4 loads
    while (e < end && (e & 3)) {
        edge_acc(acc, __ldg(esrc + e), __ldg(ew + e), lane);
        e++;
    }
    // Main: 8 edges per iteration, 2 vector loads each for idx/weight
    for (; e + 8 <= end; e += 8) {
        const int4   sa = __ldg((const int4*)(esrc + e));
        const int4   sb = __ldg((const int4*)(esrc + e + 4));
        const float4 wa = __ldg((const float4*)(ew + e));
        const float4 wb = __ldg((const float4*)(ew + e + 4));
        edge_acc(acc, sa.x, wa.x, lane);
        edge_acc(acc, sa.y, wa.y, lane);
        edge_acc(acc, sa.z, wa.z, lane);
        edge_acc(acc, sa.w, wa.w, lane);
        edge_acc(acc, sb.x, wb.x, lane);
        edge_acc(acc, sb.y, wb.y, lane);
        edge_acc(acc, sb.z, wb.z, lane);
        edge_acc(acc, sb.w, wb.w, lane);
    }
    // Mid: one 4-edge block
    for (; e + 4 <= end; e += 4) {
        const int4   sa = __ldg((const int4*)(esrc + e));
        const float4 wa = __ldg((const float4*)(ew + e));
        edge_acc(acc, sa.x, wa.x, lane);
        edge_acc(acc, sa.y, wa.y, lane);
        edge_acc(acc, sa.z, wa.z, lane);
        edge_acc(acc, sa.w, wa.w, lane);
    }
    // Tail
    for (; e < end; e++)
        edge_acc(acc, __ldg(esrc + e), __ldg(ew + e), lane);

    *(float4*)(out + (size_t)warp * NFEAT + (size_t)lane * 4) = acc;
}

// ---------------------------------------------------------------------------
// Launch: fused prep (gemm + rowptr + filter convert) -> spmm
// ---------------------------------------------------------------------------
extern "C" void kernel_launch(void* const* d_in, const int* in_sizes, int n_in,
                              void* d_out, int out_size) {
    const float* x       = (const float*)d_in[0];
    const float* filters = (const float*)d_in[1];
    const int*   esrc    = (const int*)d_in[2];
    const int*   edst    = (const int*)d_in[3];
    const float* ew      = (const float*)d_in[4];
    float*       out     = (float*)d_out;

    const int M = in_sizes[0] / NFEAT;   // 100000 nodes
    const int E = in_sizes[4];           // 3200000 edges

    const int gblocks = (M + GB_BM - 1) / GB_BM;                 // 1563
    const int rthreads = (E + 3) / 4;
    const int rblocks = (rthreads + 255) / 256;                  // 3125
    prep_kernel<<<gblocks + rblocks, 256>>>(x, filters, edst, M, E, gblocks);

    const long long nthreads = (long long)M * 32;
    spmm_kernel<<<(int)((nthreads + 255) / 256), 256>>>(esrc, ew, out, M);
}